// round 4
// baseline (speedup 1.0000x reference)
#include <cuda_runtime.h>

// Fixed shapes
#define NB      64
#define T_LEN   2048
#define DDIM    80
#define N_ROWS  (NB * T_LEN)          // 131072
#define N_ELEM  (N_ROWS * DDIM)       // 10,485,760
#define VPR     (DDIM / 4)            // 20 float4 per row

#define BX      20                    // one thread per float4 slot (no div!)
#define BY      16                    // rows per block
#define NTHREADS (BX * BY)            // 320
#define NWARPS  (NTHREADS / 32)       // 10
#define GBLOCKS (N_ROWS / BY)         // 8192

// Scratch (no device allocation allowed)
__device__ float        g_pc[GBLOCKS];
__device__ float        g_pl[GBLOCKS];
__device__ unsigned int g_count = 0;
__device__ __align__(16) float g_zero[DDIM];   // zero-initialized row

__device__ __forceinline__ float ex2f(float x) {
    float y; asm("ex2.approx.f32 %0, %1;" : "=f"(y) : "f"(x)); return y;
}
__device__ __forceinline__ float lg2f(float x) {
    float y; asm("lg2.approx.f32 %0, %1;" : "=f"(y) : "f"(x)); return y;
}

// One element: 9 shifted abs-diffs -> softmin partials (round-1 proven form)
__device__ __forceinline__ void elem(float xv,
                                     float u0, float u1, float u2,
                                     float m0, float m1, float m2,
                                     float b0, float b1, float b2,
                                     float& accC, float& accL)
{
    const float C = -46.166241308446828f;   // -32 * log2(e)
    float dc = xv - m1;                     // center (unshifted) diff
    float e0 = ex2f(C * fabsf(xv - u0));
    float e1 = ex2f(C * fabsf(xv - u1));
    float e2 = ex2f(C * fabsf(xv - u2));
    float e3 = ex2f(C * fabsf(xv - m0));
    float e4 = ex2f(C * fabsf(dc));
    float e5 = ex2f(C * fabsf(xv - m2));
    float e6 = ex2f(C * fabsf(xv - b0));
    float e7 = ex2f(C * fabsf(xv - b1));
    float e8 = ex2f(C * fabsf(xv - b2));
    float s = (((e0 + e1) + (e2 + e3)) + ((e4 + e5) + (e6 + e7))) + e8;
    accC += fabsf(dc);
    accL += lg2f(fmaxf(s, 1e-37f));
}

__global__ void __launch_bounds__(NTHREADS)
jitter_fused(const float* __restrict__ in, const float* __restrict__ tg,
             float* __restrict__ out)
{
    const int      jj  = threadIdx.x;                     // 0..19, no division
    const unsigned row = blockIdx.x * BY + threadIdx.y;   // < N_ROWS
    const unsigned i   = row & (T_LEN - 1);

    const float* rowM = tg + (size_t)row * DDIM;
    const float* rowU = (i > 0)         ? rowM - DDIM : g_zero;
    const float* rowD = (i < T_LEN - 1) ? rowM + DDIM : g_zero;

    const int base = jj * 4;
    const bool lv = (jj > 0);
    const bool rv = (jj < VPR - 1);

    float4 x4 = *reinterpret_cast<const float4*>(in + (size_t)row * DDIM + base);

    float4 u4 = *reinterpret_cast<const float4*>(rowU + base);
    float4 m4 = *reinterpret_cast<const float4*>(rowM + base);
    float4 b4 = *reinterpret_cast<const float4*>(rowD + base);

    float uL = lv ? rowU[base - 1] : 0.0f;
    float mL = lv ? rowM[base - 1] : 0.0f;
    float bL = lv ? rowD[base - 1] : 0.0f;
    float uR = rv ? rowU[base + 4] : 0.0f;
    float mR = rv ? rowM[base + 4] : 0.0f;
    float bR = rv ? rowD[base + 4] : 0.0f;

    float accC = 0.0f;
    float accL = 0.0f;

    elem(x4.x, uL,   u4.x, u4.y,  mL,   m4.x, m4.y,  bL,   b4.x, b4.y, accC, accL);
    elem(x4.y, u4.x, u4.y, u4.z,  m4.x, m4.y, m4.z,  b4.x, b4.y, b4.z, accC, accL);
    elem(x4.z, u4.y, u4.z, u4.w,  m4.y, m4.z, m4.w,  b4.y, b4.z, b4.w, accC, accL);
    elem(x4.w, u4.z, u4.w, uR,    m4.z, m4.w, mR,    b4.z, b4.w, bR,   accC, accL);

    // ---- deterministic in-block reduction: shuffle within warp, smem across
    const int tid  = threadIdx.y * BX + threadIdx.x;
    const int lane = tid & 31;
    const int wid  = tid >> 5;

    #pragma unroll
    for (int off = 16; off > 0; off >>= 1) {
        accC += __shfl_down_sync(0xFFFFFFFFu, accC, off);
        accL += __shfl_down_sync(0xFFFFFFFFu, accL, off);
    }

    __shared__ float shc[NWARPS];
    __shared__ float shl[NWARPS];
    if (lane == 0) { shc[wid] = accC; shl[wid] = accL; }
    __syncthreads();

    __shared__ bool isLast;
    if (tid == 0) {
        float sc = shc[0], sl = shl[0];
        #pragma unroll
        for (int w = 1; w < NWARPS; w++) { sc += shc[w]; sl += shl[w]; }
        g_pc[blockIdx.x] = sc;
        g_pl[blockIdx.x] = sl;
        __threadfence();
        unsigned ticket = atomicAdd(&g_count, 1u);
        isLast = (ticket == GBLOCKS - 1);
    }
    __syncthreads();

    if (isLast) {
        // last block: deterministic final sum over fixed index order
        double dc = 0.0, dl = 0.0;
        for (int k = tid; k < GBLOCKS; k += NTHREADS) {
            dc += (double)__ldcg(&g_pc[k]);
            dl += (double)__ldcg(&g_pl[k]);
        }
        // warp reduce doubles via shfl on hi/lo is messy; use smem tree
        __shared__ double dsc[NTHREADS];
        __shared__ double dsl[NTHREADS];
        dsc[tid] = dc; dsl[tid] = dl;
        __syncthreads();
        // 320 = 64*5: first fold 320 -> 64 (tid < 64 sums 5 strided slots)
        if (tid < 64) {
            double c = dsc[tid], l = dsl[tid];
            #pragma unroll
            for (int k = 1; k < 5; k++) { c += dsc[tid + 64 * k]; l += dsl[tid + 64 * k]; }
            dsc[tid] = c; dsl[tid] = l;
        }
        __syncthreads();
        #pragma unroll
        for (int off = 32; off > 0; off >>= 1) {
            if (tid < off) {
                dsc[tid] += dsc[tid + off];
                dsl[tid] += dsl[tid + off];
            }
            __syncthreads();
        }
        if (tid == 0) {
            const double Ad  = 46.166241308446828;   // 32*log2(e)
            const double C2d = -0.021660849392498291; // -ln(2)/32
            // accC was accumulated as |x - t| scaled? No: C-form keeps raw units.
            double res = (0.5 / (double)N_ELEM) * (dsc[0] + C2d * dsl[0]);
            (void)Ad;
            out[0] = (float)res;
            g_count = 0;   // reset ticket for graph replay
        }
    }
}

extern "C" void kernel_launch(void* const* d_in, const int* in_sizes, int n_in,
                              void* d_out, int out_size)
{
    const float* in = (const float*)d_in[0];
    const float* tg = (const float*)d_in[1];
    float* out = (float*)d_out;

    dim3 block(BX, BY);
    jitter_fused<<<GBLOCKS, block>>>(in, tg, out);
}

// round 5
// speedup vs baseline: 1.0232x; 1.0232x over previous
#include <cuda_runtime.h>

// Fixed shapes
#define NB      64
#define T_LEN   2048
#define DDIM    80
#define N_ROWS  (NB * T_LEN)          // 131072
#define N_ELEM  (N_ROWS * DDIM)       // 10,485,760
#define VPR     (DDIM / 4)            // 20 float4 per row

#define BX      20                    // one thread per float4 slot (no div!)
#define BY      16                    // rows per block
#define NTHREADS (BX * BY)            // 320
#define NWARPS  (NTHREADS / 32)       // 10
#define GBLOCKS (N_ROWS / BY)         // 8192

// Scratch (no device allocation allowed)
__device__ float        g_pc[GBLOCKS];
__device__ float        g_pl[GBLOCKS];
__device__ unsigned int g_count = 0;
__device__ __align__(16) float g_zero[DDIM];   // zero-initialized row

__device__ __forceinline__ float ex2f(float x) {
    float y; asm("ex2.approx.f32 %0, %1;" : "=f"(y) : "f"(x)); return y;
}
__device__ __forceinline__ float lg2f(float x) {
    float y; asm("lg2.approx.f32 %0, %1;" : "=f"(y) : "f"(x)); return y;
}

// One element: 9 shifted abs-diffs -> softmin partials (round-1 proven form)
__device__ __forceinline__ void elem(float xv,
                                     float u0, float u1, float u2,
                                     float m0, float m1, float m2,
                                     float b0, float b1, float b2,
                                     float& accC, float& accL)
{
    const float C = -46.166241308446828f;   // -32 * log2(e)
    float dc = xv - m1;                     // center (unshifted) diff
    float e0 = ex2f(C * fabsf(xv - u0));
    float e1 = ex2f(C * fabsf(xv - u1));
    float e2 = ex2f(C * fabsf(xv - u2));
    float e3 = ex2f(C * fabsf(xv - m0));
    float e4 = ex2f(C * fabsf(dc));
    float e5 = ex2f(C * fabsf(xv - m2));
    float e6 = ex2f(C * fabsf(xv - b0));
    float e7 = ex2f(C * fabsf(xv - b1));
    float e8 = ex2f(C * fabsf(xv - b2));
    float s = (((e0 + e1) + (e2 + e3)) + ((e4 + e5) + (e6 + e7))) + e8;
    accC += fabsf(dc);
    accL += lg2f(fmaxf(s, 1e-37f));
}

__global__ void __launch_bounds__(NTHREADS)
jitter_fused(const float* __restrict__ in, const float* __restrict__ tg,
             float* __restrict__ out)
{
    const int      jj  = threadIdx.x;                     // 0..19, no division
    const unsigned row = blockIdx.x * BY + threadIdx.y;   // < N_ROWS
    const unsigned i   = row & (T_LEN - 1);

    const float* rowM = tg + (size_t)row * DDIM;
    const float* rowU = (i > 0)         ? rowM - DDIM : g_zero;
    const float* rowD = (i < T_LEN - 1) ? rowM + DDIM : g_zero;

    const int base = jj * 4;
    const bool lv = (jj > 0);
    const bool rv = (jj < VPR - 1);

    float4 x4 = *reinterpret_cast<const float4*>(in + (size_t)row * DDIM + base);

    float4 u4 = *reinterpret_cast<const float4*>(rowU + base);
    float4 m4 = *reinterpret_cast<const float4*>(rowM + base);
    float4 b4 = *reinterpret_cast<const float4*>(rowD + base);

    float uL = lv ? rowU[base - 1] : 0.0f;
    float mL = lv ? rowM[base - 1] : 0.0f;
    float bL = lv ? rowD[base - 1] : 0.0f;
    float uR = rv ? rowU[base + 4] : 0.0f;
    float mR = rv ? rowM[base + 4] : 0.0f;
    float bR = rv ? rowD[base + 4] : 0.0f;

    float accC = 0.0f;
    float accL = 0.0f;

    elem(x4.x, uL,   u4.x, u4.y,  mL,   m4.x, m4.y,  bL,   b4.x, b4.y, accC, accL);
    elem(x4.y, u4.x, u4.y, u4.z,  m4.x, m4.y, m4.z,  b4.x, b4.y, b4.z, accC, accL);
    elem(x4.z, u4.y, u4.z, u4.w,  m4.y, m4.z, m4.w,  b4.y, b4.z, b4.w, accC, accL);
    elem(x4.w, u4.z, u4.w, uR,    m4.z, m4.w, mR,    b4.z, b4.w, bR,   accC, accL);

    // ---- deterministic in-block reduction: shuffle within warp, smem across
    const int tid  = threadIdx.y * BX + threadIdx.x;
    const int lane = tid & 31;
    const int wid  = tid >> 5;

    #pragma unroll
    for (int off = 16; off > 0; off >>= 1) {
        accC += __shfl_down_sync(0xFFFFFFFFu, accC, off);
        accL += __shfl_down_sync(0xFFFFFFFFu, accL, off);
    }

    __shared__ float shc[NWARPS];
    __shared__ float shl[NWARPS];
    if (lane == 0) { shc[wid] = accC; shl[wid] = accL; }
    __syncthreads();

    __shared__ bool isLast;
    if (tid == 0) {
        float sc = shc[0], sl = shl[0];
        #pragma unroll
        for (int w = 1; w < NWARPS; w++) { sc += shc[w]; sl += shl[w]; }
        g_pc[blockIdx.x] = sc;
        g_pl[blockIdx.x] = sl;
        __threadfence();
        unsigned ticket = atomicAdd(&g_count, 1u);
        isLast = (ticket == GBLOCKS - 1);
    }
    __syncthreads();

    if (isLast) {
        // last block: deterministic final sum over fixed index order
        double dc = 0.0, dl = 0.0;
        for (int k = tid; k < GBLOCKS; k += NTHREADS) {
            dc += (double)__ldcg(&g_pc[k]);
            dl += (double)__ldcg(&g_pl[k]);
        }
        // warp reduce doubles via shfl on hi/lo is messy; use smem tree
        __shared__ double dsc[NTHREADS];
        __shared__ double dsl[NTHREADS];
        dsc[tid] = dc; dsl[tid] = dl;
        __syncthreads();
        // 320 = 64*5: first fold 320 -> 64 (tid < 64 sums 5 strided slots)
        if (tid < 64) {
            double c = dsc[tid], l = dsl[tid];
            #pragma unroll
            for (int k = 1; k < 5; k++) { c += dsc[tid + 64 * k]; l += dsl[tid + 64 * k]; }
            dsc[tid] = c; dsl[tid] = l;
        }
        __syncthreads();
        #pragma unroll
        for (int off = 32; off > 0; off >>= 1) {
            if (tid < off) {
                dsc[tid] += dsc[tid + off];
                dsl[tid] += dsl[tid + off];
            }
            __syncthreads();
        }
        if (tid == 0) {
            const double Ad  = 46.166241308446828;   // 32*log2(e)
            const double C2d = -0.021660849392498291; // -ln(2)/32
            // accC was accumulated as |x - t| scaled? No: C-form keeps raw units.
            double res = (0.5 / (double)N_ELEM) * (dsc[0] + C2d * dsl[0]);
            (void)Ad;
            out[0] = (float)res;
            g_count = 0;   // reset ticket for graph replay
        }
    }
}

extern "C" void kernel_launch(void* const* d_in, const int* in_sizes, int n_in,
                              void* d_out, int out_size)
{
    const float* in = (const float*)d_in[0];
    const float* tg = (const float*)d_in[1];
    float* out = (float*)d_out;

    dim3 block(BX, BY);
    jitter_fused<<<GBLOCKS, block>>>(in, tg, out);
}